// round 7
// baseline (speedup 1.0000x reference)
#include <cuda_runtime.h>
#include <math.h>

// Problem constants
#define B_    4
#define T_    2048
#define D_    1024
#define H_    16
#define HD_   64
#define FFN_  4096
#define ROWS_ (B_ * T_)        // 8192

// ---------------------------------------------------------------------------
// Scratch (device globals -- allocation inside kernel_launch is forbidden)
// ---------------------------------------------------------------------------
__device__ float g_x [ROWS_ * D_];    // LN1 output (tf32-rounded)
__device__ float g_q [ROWS_ * D_];
__device__ float g_k [ROWS_ * D_];
__device__ float g_v [ROWS_ * D_];
__device__ float g_o [ROWS_ * D_];    // attention output (tf32-rounded)
__device__ float g_h2[ROWS_ * D_];    // h + o@wo (full fp32)
__device__ float g_y [ROWS_ * D_];    // LN2 output (tf32-rounded)
__device__ float g_a [ROWS_ * FFN_];  // y@w1 (then tf32(silu(a)*g) in place)
__device__ float g_g [ROWS_ * FFN_];  // y@w2

// tf32-rounded weight copies
__device__ float g_wq [D_ * D_];
__device__ float g_wk [D_ * D_];
__device__ float g_wv [D_ * D_];
__device__ float g_wo [D_ * D_];
__device__ float g_w1 [D_ * FFN_];
__device__ float g_w2 [D_ * FFN_];
__device__ float g_wout[FFN_ * D_];

// ---------------------------------------------------------------------------
// Helpers
// ---------------------------------------------------------------------------
__device__ __forceinline__ float f2tf32f(float x) {
    unsigned u;
    asm("cvt.rna.tf32.f32 %0, %1;" : "=r"(u) : "f"(x));
    return __uint_as_float(u);
}

__device__ __forceinline__ void mma_tf32(float c[4],
                                         unsigned a0, unsigned a1, unsigned a2, unsigned a3,
                                         unsigned b0, unsigned b1) {
    asm volatile(
        "mma.sync.aligned.m16n8k8.row.col.f32.tf32.tf32.f32 "
        "{%0,%1,%2,%3}, {%4,%5,%6,%7}, {%8,%9}, {%0,%1,%2,%3};"
        : "+f"(c[0]), "+f"(c[1]), "+f"(c[2]), "+f"(c[3])
        : "r"(a0), "r"(a1), "r"(a2), "r"(a3), "r"(b0), "r"(b1));
}

__device__ __forceinline__ void cp16(unsigned dst, const void* src) {
    asm volatile("cp.async.cg.shared.global [%0], [%1], 16;" :: "r"(dst), "l"(src));
}
#define CP_COMMIT() asm volatile("cp.async.commit_group;" ::: "memory")
template <int N> __device__ __forceinline__ void cp_wait() {
    asm volatile("cp.async.wait_group %0;" :: "n"(N) : "memory");
}

// ---------------------------------------------------------------------------
// Round a buffer to tf32 (for weights)
// ---------------------------------------------------------------------------
__global__ void round_kernel(const float* __restrict__ in, float* __restrict__ out)
{
    int i = blockIdx.x * blockDim.x + threadIdx.x;
    float4 v = reinterpret_cast<const float4*>(in)[i];
    v.x = f2tf32f(v.x); v.y = f2tf32f(v.y);
    v.z = f2tf32f(v.z); v.w = f2tf32f(v.w);
    reinterpret_cast<float4*>(out)[i] = v;
}

// ---------------------------------------------------------------------------
// LayerNorm: one block (256 threads) per row of 1024; output tf32-rounded
// ---------------------------------------------------------------------------
__global__ void ln_kernel(const float* __restrict__ in,
                          const float* __restrict__ gam,
                          const float* __restrict__ bet,
                          float* __restrict__ out)
{
    __shared__ float r1[8], r2[8];
    __shared__ float s_mu, s_rstd;
    int row = blockIdx.x, tid = threadIdx.x;

    const float4* p = reinterpret_cast<const float4*>(in) + (size_t)row * (D_ / 4);
    float4 v = p[tid];
    float s  = v.x + v.y + v.z + v.w;
    float s2 = v.x * v.x + v.y * v.y + v.z * v.z + v.w * v.w;
    #pragma unroll
    for (int o = 16; o; o >>= 1) {
        s  += __shfl_xor_sync(0xffffffffu, s,  o);
        s2 += __shfl_xor_sync(0xffffffffu, s2, o);
    }
    if ((tid & 31) == 0) { r1[tid >> 5] = s; r2[tid >> 5] = s2; }
    __syncthreads();
    if (tid == 0) {
        float a = 0.f, b = 0.f;
        #pragma unroll
        for (int i = 0; i < 8; i++) { a += r1[i]; b += r2[i]; }
        float mu  = a / (float)D_;
        float var = b / (float)D_ - mu * mu;
        s_mu = mu;
        s_rstd = rsqrtf(var + 1e-5f);
    }
    __syncthreads();
    float mu = s_mu, rs = s_rstd;
    float4 g4 = reinterpret_cast<const float4*>(gam)[tid];
    float4 b4 = reinterpret_cast<const float4*>(bet)[tid];
    float4 o;
    o.x = f2tf32f((v.x - mu) * rs * g4.x + b4.x);
    o.y = f2tf32f((v.y - mu) * rs * g4.y + b4.y);
    o.z = f2tf32f((v.z - mu) * rs * g4.z + b4.z);
    o.w = f2tf32f((v.w - mu) * rs * g4.w + b4.w);
    reinterpret_cast<float4*>(out)[(size_t)row * (D_ / 4) + tid] = o;
}

// ---------------------------------------------------------------------------
// TF32 tensor-core GEMM, 3-stage cp.async pipeline, 128x256 block tile.
// C[M,N] = A[M,K] @ W[K,N] (+R). BK=16, 8 warps as 2(m) x 4(n),
// warp tile 64x64 via mma.m16n8k8 (4 mf x 8 nf) -> 1.0 LDS per MMA.
// A smem: [m][k] rows of 16, stride 20 floats (conflict-free frag reads).
// B smem: [k][n] rows of 256, stride 264 floats (conflict-free frag reads).
// Inputs must be pre-rounded to tf32 (raw bits consumed as tf32).
// NGEM selects W/C by blockIdx.z (QKV / w1w2 fusion).
// ---------------------------------------------------------------------------
#define AST_ 20
#define BST_ 264
#define ATILE_ (128 * AST_)   // floats per A stage (2560)
#define BTILE_ (16 * BST_)    // floats per B stage (4224)
#define GEMM_SMEM (3 * (ATILE_ + BTILE_) * 4)   // 81408 bytes

template <bool RES, int NGEM>
__global__ void __launch_bounds__(256, 1)
tgemm_kernel(const float* __restrict__ A,
             const float* __restrict__ W0, const float* __restrict__ W1,
             const float* __restrict__ W2,
             const float* __restrict__ R,
             float* __restrict__ C0, float* __restrict__ C1, float* __restrict__ C2,
             int M, int N, int K)
{
    extern __shared__ float sm[];
    float* As = sm;                    // [3][ATILE_]
    float* Bs = sm + 3 * ATILE_;       // [3][BTILE_]

    const float* W = W0;
    float* C = C0;
    if (NGEM >= 2) {
        int z = blockIdx.z;
        W = (z == 0) ? W0 : (z == 1) ? W1 : W2;
        C = (z == 0) ? C0 : (z == 1) ? C1 : C2;
    }

    const int tid  = threadIdx.x;
    const int lane = tid & 31;
    const int warp = tid >> 5;
    const int wm   = (warp >> 2) * 64;   // warp m-offset (0,64)
    const int wn   = (warp & 3) * 64;    // warp n-offset (0,64,128,192)
    const int qm   = lane >> 2;          // 0..7
    const int qk   = lane & 3;           // 0..3

    const int bm = blockIdx.y * 128, bn = blockIdx.x * 256;

    // cp.async assignments: A 2 chunks (tid>>2 rows, (tid&3)*4 seg),
    // B 4 chunks (rows tid>>6 + 4r, seg (tid&63)*4)
    const int arow0 = tid >> 2;          // 0..63  (and +64)
    const int aseg  = (tid & 3) * 4;     // 0,4,8,12
    const int brow0 = tid >> 6;          // 0..3   (+4,+8,+12)
    const int bseg  = (tid & 63) * 4;    // 0..252

    const float* Abase = A + (size_t)bm * K;
    const float* Wbase = W + bn;

    float acc[4][8][4];
    #pragma unroll
    for (int i = 0; i < 4; i++)
        #pragma unroll
        for (int j = 0; j < 8; j++)
            #pragma unroll
            for (int r = 0; r < 4; r++) acc[i][j][r] = 0.f;

    auto issue_tile = [&](int kt, int st) {
        unsigned abase = (unsigned)__cvta_generic_to_shared(&As[st * ATILE_]);
        unsigned bbase = (unsigned)__cvta_generic_to_shared(&Bs[st * BTILE_]);
        const float* Ag = Abase + kt * 16;
        const float* Bg = Wbase + (size_t)(kt * 16) * N;
        cp16(abase + (unsigned)(arow0 * AST_ + aseg) * 4,
             Ag + (size_t)arow0 * K + aseg);
        cp16(abase + (unsigned)((arow0 + 64) * AST_ + aseg) * 4,
             Ag + (size_t)(arow0 + 64) * K + aseg);
        #pragma unroll
        for (int r = 0; r < 4; r++) {
            int row = brow0 + 4 * r;
            cp16(bbase + (unsigned)(row * BST_ + bseg) * 4,
                 Bg + (size_t)row * N + bseg);
        }
        CP_COMMIT();
    };

    const int ntiles = K / 16;   // >= 64

    issue_tile(0, 0);
    issue_tile(1, 1);
    cp_wait<1>();
    __syncthreads();

    for (int it = 0; it < ntiles; it++) {
        const int s = it % 3;

        if (it + 2 < ntiles) issue_tile(it + 2, (it + 2) % 3);

        const float* Asb = &As[s * ATILE_];
        const float* Bsb = &Bs[s * BTILE_];

        #pragma unroll
        for (int kt = 0; kt < 2; kt++) {
            const int ksb = kt * 8;
            unsigned af[4][4];
            #pragma unroll
            for (int mf = 0; mf < 4; mf++) {
                int m = wm + mf * 16 + qm;
                af[mf][0] = __float_as_uint(Asb[(size_t)m * AST_ + ksb + qk]);
                af[mf][1] = __float_as_uint(Asb[(size_t)(m + 8) * AST_ + ksb + qk]);
                af[mf][2] = __float_as_uint(Asb[(size_t)m * AST_ + ksb + qk + 4]);
                af[mf][3] = __float_as_uint(Asb[(size_t)(m + 8) * AST_ + ksb + qk + 4]);
            }
            unsigned bf[8][2];
            #pragma unroll
            for (int nf = 0; nf < 8; nf++) {
                int n = wn + nf * 8 + qm;
                bf[nf][0] = __float_as_uint(Bsb[(size_t)(ksb + qk) * BST_ + n]);
                bf[nf][1] = __float_as_uint(Bsb[(size_t)(ksb + qk + 4) * BST_ + n]);
            }
            #pragma unroll
            for (int mf = 0; mf < 4; mf++)
                #pragma unroll
                for (int nf = 0; nf < 8; nf++)
                    mma_tf32(acc[mf][nf], af[mf][0], af[mf][1], af[mf][2], af[mf][3],
                             bf[nf][0], bf[nf][1]);
        }

        if (it + 2 < ntiles)       cp_wait<1>();
        else if (it + 1 < ntiles)  cp_wait<0>();
        __syncthreads();
    }

    // epilogue: c0,c1 -> (row, 2qk..2qk+1), c2,c3 -> (row+8, same cols)
    #pragma unroll
    for (int mf = 0; mf < 4; mf++) {
        int row0 = bm + wm + mf * 16 + qm;
        #pragma unroll
        for (int nf = 0; nf < 8; nf++) {
            int col = bn + wn + nf * 8 + 2 * qk;
            size_t off0 = (size_t)row0 * N + col;
            size_t off1 = (size_t)(row0 + 8) * N + col;
            float2 o0 = make_float2(acc[mf][nf][0], acc[mf][nf][1]);
            float2 o1 = make_float2(acc[mf][nf][2], acc[mf][nf][3]);
            if (RES) {
                float2 r0 = *reinterpret_cast<const float2*>(R + off0);
                float2 r1 = *reinterpret_cast<const float2*>(R + off1);
                o0.x += r0.x; o0.y += r0.y;
                o1.x += r1.x; o1.y += r1.y;
            }
            *reinterpret_cast<float2*>(C + off0) = o0;
            *reinterpret_cast<float2*>(C + off1) = o1;
        }
    }
}

// ---------------------------------------------------------------------------
// Flash attention (causal): grid = (T/64, B*H), 256 threads. tf32-rounded out.
// ---------------------------------------------------------------------------
#define ATTN_SMEM ((64 * 64 + 64 * 65 + 64 * 64) * 4)

__global__ void __launch_bounds__(256)
attn_kernel(const float* __restrict__ Q, const float* __restrict__ K,
            const float* __restrict__ V, float* __restrict__ O)
{
    extern __shared__ float smf[];
    float* Qs  = smf;                // [64][64]
    float* Kts = smf + 64 * 64;      // [64][65]  (transposed K; aliased as P)
    float* Vs  = Kts + 64 * 65;      // [64][64]

    int tid = threadIdx.x;
    int ty = tid >> 4, tx = tid & 15;
    int b = blockIdx.y >> 4, h = blockIdx.y & 15;
    int qb = blockIdx.x * 64;

    const float* Qb = Q + (size_t)b * T_ * D_ + h * HD_;
    const float* Kb = K + (size_t)b * T_ * D_ + h * HD_;
    const float* Vb = V + (size_t)b * T_ * D_ + h * HD_;

    int ltok = tid >> 4;
    int ld0  = (tid & 15) * 4;

    #pragma unroll
    for (int rep = 0; rep < 4; rep++) {
        int t = rep * 16 + ltok;
        float4 qv = *reinterpret_cast<const float4*>(Qb + (size_t)(qb + t) * D_ + ld0);
        *reinterpret_cast<float4*>(&Qs[t * 64 + ld0]) = qv;
    }

    float acc[4][4];
    float m_i[4], l_i[4];
    #pragma unroll
    for (int i = 0; i < 4; i++) {
        m_i[i] = -1e30f; l_i[i] = 0.f;
        #pragma unroll
        for (int j = 0; j < 4; j++) acc[i][j] = 0.f;
    }

    int ntile = blockIdx.x + 1;
    for (int j = 0; j < ntile; j++) {
        int jb = j * 64;
        __syncthreads();
        #pragma unroll
        for (int rep = 0; rep < 4; rep++) {
            int t = rep * 16 + ltok;
            float4 kv = *reinterpret_cast<const float4*>(Kb + (size_t)(jb + t) * D_ + ld0);
            Kts[(ld0 + 0) * 65 + t] = kv.x;
            Kts[(ld0 + 1) * 65 + t] = kv.y;
            Kts[(ld0 + 2) * 65 + t] = kv.z;
            Kts[(ld0 + 3) * 65 + t] = kv.w;
            float4 vv = *reinterpret_cast<const float4*>(Vb + (size_t)(jb + t) * D_ + ld0);
            *reinterpret_cast<float4*>(&Vs[t * 64 + ld0]) = vv;
        }
        __syncthreads();

        float s[4][4];
        #pragma unroll
        for (int i = 0; i < 4; i++)
            #pragma unroll
            for (int jj = 0; jj < 4; jj++) s[i][jj] = 0.f;

        #pragma unroll 4
        for (int d = 0; d < 64; d++) {
            float a0 = Qs[(ty * 4 + 0) * 64 + d];
            float a1 = Qs[(ty * 4 + 1) * 64 + d];
            float a2 = Qs[(ty * 4 + 2) * 64 + d];
            float a3 = Qs[(ty * 4 + 3) * 64 + d];
            float b0 = Kts[d * 65 + tx * 4 + 0];
            float b1 = Kts[d * 65 + tx * 4 + 1];
            float b2 = Kts[d * 65 + tx * 4 + 2];
            float b3 = Kts[d * 65 + tx * 4 + 3];
            s[0][0] += a0 * b0; s[0][1] += a0 * b1; s[0][2] += a0 * b2; s[0][3] += a0 * b3;
            s[1][0] += a1 * b0; s[1][1] += a1 * b1; s[1][2] += a1 * b2; s[1][3] += a1 * b3;
            s[2][0] += a2 * b0; s[2][1] += a2 * b1; s[2][2] += a2 * b2; s[2][3] += a2 * b3;
            s[3][0] += a3 * b0; s[3][1] += a3 * b1; s[3][2] += a3 * b2; s[3][3] += a3 * b3;
        }

        bool diag = (jb == qb);
        #pragma unroll
        for (int i = 0; i < 4; i++)
            #pragma unroll
            for (int jj = 0; jj < 4; jj++) {
                float sv = s[i][jj] * 0.125f;
                if (diag && (tx * 4 + jj > ty * 4 + i)) sv = -1e30f;
                s[i][jj] = sv;
            }

        __syncthreads();

        #pragma unroll
        for (int i = 0; i < 4; i++) {
            float mx = fmaxf(fmaxf(s[i][0], s[i][1]), fmaxf(s[i][2], s[i][3]));
            #pragma unroll
            for (int o = 1; o < 16; o <<= 1) mx = fmaxf(mx, __shfl_xor_sync(0xffffffffu, mx, o));
            float mn = fmaxf(m_i[i], mx);
            float p0 = __expf(s[i][0] - mn);
            float p1 = __expf(s[i][1] - mn);
            float p2 = __expf(s[i][2] - mn);
            float p3 = __expf(s[i][3] - mn);
            float sum = p0 + p1 + p2 + p3;
            #pragma unroll
            for (int o = 1; o < 16; o <<= 1) sum += __shfl_xor_sync(0xffffffffu, sum, o);
            float al = __expf(m_i[i] - mn);
            l_i[i] = l_i[i] * al + sum;
            m_i[i] = mn;
            acc[i][0] *= al; acc[i][1] *= al; acc[i][2] *= al; acc[i][3] *= al;
            float* Ps = Kts;
            Ps[(ty * 4 + i) * 65 + tx * 4 + 0] = p0;
            Ps[(ty * 4 + i) * 65 + tx * 4 + 1] = p1;
            Ps[(ty * 4 + i) * 65 + tx * 4 + 2] = p2;
            Ps[(ty * 4 + i) * 65 + tx * 4 + 3] = p3;
        }
        __syncthreads();

        #pragma unroll 4
        for (int c = 0; c < 64; c++) {
            float p0 = Kts[(ty * 4 + 0) * 65 + c];
            float p1 = Kts[(ty * 4 + 1) * 65 + c];
            float p2 = Kts[(ty * 4 + 2) * 65 + c];
            float p3 = Kts[(ty * 4 + 3) * 65 + c];
            float4 vv = *reinterpret_cast<const float4*>(&Vs[c * 64 + tx * 4]);
            acc[0][0] += p0 * vv.x; acc[0][1] += p0 * vv.y; acc[0][2] += p0 * vv.z; acc[0][3] += p0 * vv.w;
            acc[1][0] += p1 * vv.x; acc[1][1] += p1 * vv.y; acc[1][2] += p1 * vv.z; acc[1][3] += p1 * vv.w;
            acc[2][0] += p2 * vv.x; acc[2][1] += p2 * vv.y; acc[2][2] += p2 * vv.z; acc[2][3] += p2 * vv.w;
            acc[3][0] += p3 * vv.x; acc[3][1] += p3 * vv.y; acc[3][2] += p3 * vv.z; acc[3][3] += p3 * vv.w;
        }
    }

    #pragma unroll
    for (int i = 0; i < 4; i++) {
        float inv = 1.0f / l_i[i];
        float4 o = make_float4(f2tf32f(acc[i][0] * inv), f2tf32f(acc[i][1] * inv),
                               f2tf32f(acc[i][2] * inv), f2tf32f(acc[i][3] * inv));
        *reinterpret_cast<float4*>(const_cast<float*>(
            O + (size_t)b * T_ * D_ + h * HD_ + (size_t)(qb + ty * 4 + i) * D_ + tx * 4)) = o;
    }
}

// ---------------------------------------------------------------------------
// a = tf32(silu(a) * g)
// ---------------------------------------------------------------------------
__global__ void silu_mul_kernel(float* __restrict__ a, const float* __restrict__ g)
{
    int i = blockIdx.x * blockDim.x + threadIdx.x;
    float4 av = reinterpret_cast<float4*>(a)[i];
    float4 gv = reinterpret_cast<const float4*>(g)[i];
    av.x = f2tf32f(av.x / (1.f + __expf(-av.x)) * gv.x);
    av.y = f2tf32f(av.y / (1.f + __expf(-av.y)) * gv.y);
    av.z = f2tf32f(av.z / (1.f + __expf(-av.z)) * gv.z);
    av.w = f2tf32f(av.w / (1.f + __expf(-av.w)) * gv.w);
    reinterpret_cast<float4*>(a)[i] = av;
}

// ---------------------------------------------------------------------------
// Orchestration
// ---------------------------------------------------------------------------
extern "C" void kernel_launch(void* const* d_in, const int* in_sizes, int n_in,
                              void* d_out, int out_size)
{
    const float* h    = (const float*)d_in[0];
    const float* alng = (const float*)d_in[2];
    const float* alnb = (const float*)d_in[3];
    const float* mlng = (const float*)d_in[4];
    const float* mlnb = (const float*)d_in[5];
    const float* wq   = (const float*)d_in[6];
    const float* wk   = (const float*)d_in[7];
    const float* wv   = (const float*)d_in[8];
    const float* wo   = (const float*)d_in[9];
    const float* w1   = (const float*)d_in[10];
    const float* w2   = (const float*)d_in[11];
    const float* wout = (const float*)d_in[12];
    float* out = (float*)d_out;

    float *px, *pq, *pk, *pv, *po, *ph2, *py, *pa, *pg;
    float *rwq, *rwk, *rwv, *rwo, *rw1, *rw2, *rwout;
    cudaGetSymbolAddress((void**)&px,  g_x);
    cudaGetSymbolAddress((void**)&pq,  g_q);
    cudaGetSymbolAddress((void**)&pk,  g_k);
    cudaGetSymbolAddress((void**)&pv,  g_v);
    cudaGetSymbolAddress((void**)&po,  g_o);
    cudaGetSymbolAddress((void**)&ph2, g_h2);
    cudaGetSymbolAddress((void**)&py,  g_y);
    cudaGetSymbolAddress((void**)&pa,  g_a);
    cudaGetSymbolAddress((void**)&pg,  g_g);
    cudaGetSymbolAddress((void**)&rwq,   g_wq);
    cudaGetSymbolAddress((void**)&rwk,   g_wk);
    cudaGetSymbolAddress((void**)&rwv,   g_wv);
    cudaGetSymbolAddress((void**)&rwo,   g_wo);
    cudaGetSymbolAddress((void**)&rw1,   g_w1);
    cudaGetSymbolAddress((void**)&rw2,   g_w2);
    cudaGetSymbolAddress((void**)&rwout, g_wout);

    cudaFuncSetAttribute(attn_kernel, cudaFuncAttributeMaxDynamicSharedMemorySize, ATTN_SMEM);
    cudaFuncSetAttribute(tgemm_kernel<false, 3>, cudaFuncAttributeMaxDynamicSharedMemorySize, GEMM_SMEM);
    cudaFuncSetAttribute(tgemm_kernel<false, 2>, cudaFuncAttributeMaxDynamicSharedMemorySize, GEMM_SMEM);
    cudaFuncSetAttribute(tgemm_kernel<false, 1>, cudaFuncAttributeMaxDynamicSharedMemorySize, GEMM_SMEM);
    cudaFuncSetAttribute(tgemm_kernel<true, 1>,  cudaFuncAttributeMaxDynamicSharedMemorySize, GEMM_SMEM);

    // tf32-round all weights (small BW-bound passes)
    round_kernel<<<(D_ * D_ / 4) / 256, 256>>>(wq, rwq);
    round_kernel<<<(D_ * D_ / 4) / 256, 256>>>(wk, rwk);
    round_kernel<<<(D_ * D_ / 4) / 256, 256>>>(wv, rwv);
    round_kernel<<<(D_ * D_ / 4) / 256, 256>>>(wo, rwo);
    round_kernel<<<(D_ * FFN_ / 4) / 256, 256>>>(w1, rw1);
    round_kernel<<<(D_ * FFN_ / 4) / 256, 256>>>(w2, rw2);
    round_kernel<<<(FFN_ * D_ / 4) / 256, 256>>>(wout, rwout);

    dim3 gQKV(D_ / 256, ROWS_ / 128, 3);   // (4, 64, 3)
    dim3 gD(D_ / 256, ROWS_ / 128);        // (4, 64)
    dim3 gFF(FFN_ / 256, ROWS_ / 128, 2);  // (16, 64, 2)

    // x = tf32(LN(h))
    ln_kernel<<<ROWS_, 256>>>(h, alng, alnb, px);
    // q,k,v = x @ {wq,wk,wv}   (fused launch)
    tgemm_kernel<false, 3><<<gQKV, 256, GEMM_SMEM>>>(px, rwq, rwk, rwv, nullptr,
                                                     pq, pk, pv, ROWS_, D_, D_);
    // o = tf32(attention(q,k,v))
    attn_kernel<<<dim3(T_ / 64, B_ * H_), 256, ATTN_SMEM>>>(pq, pk, pv, po);
    // h2 = h + o @ wo
    tgemm_kernel<true, 1><<<gD, 256, GEMM_SMEM>>>(po, rwo, nullptr, nullptr, h,
                                                  ph2, nullptr, nullptr, ROWS_, D_, D_);
    // y = tf32(LN(h2))
    ln_kernel<<<ROWS_, 256>>>(ph2, mlng, mlnb, py);
    // a = y@w1 ; g = y@w2   (fused launch)
    tgemm_kernel<false, 2><<<gFF, 256, GEMM_SMEM>>>(py, rw1, rw2, nullptr, nullptr,
                                                    pa, pg, nullptr, ROWS_, FFN_, D_);
    // a = tf32(silu(a)*g)
    silu_mul_kernel<<<(ROWS_ * FFN_ / 4) / 256, 256>>>(pa, pg);
    // out = h2 + a @ wout
    tgemm_kernel<true, 1><<<gD, 256, GEMM_SMEM>>>(pa, rwout, nullptr, nullptr, ph2,
                                                  out, nullptr, nullptr, ROWS_, D_, FFN_);
}

// round 8
// speedup vs baseline: 1.2180x; 1.2180x over previous
#include <cuda_runtime.h>
#include <math.h>

// Problem constants
#define B_    4
#define T_    2048
#define D_    1024
#define H_    16
#define HD_   64
#define FFN_  4096
#define ROWS_ (B_ * T_)        // 8192

// ---------------------------------------------------------------------------
// Scratch (device globals)
// ---------------------------------------------------------------------------
__device__ float g_x [ROWS_ * D_];
__device__ float g_q [ROWS_ * D_];
__device__ float g_k [ROWS_ * D_];
__device__ float g_v [ROWS_ * D_];
__device__ float g_o [ROWS_ * D_];
__device__ float g_h2[ROWS_ * D_];
__device__ float g_y [ROWS_ * D_];
__device__ float g_a [ROWS_ * FFN_];
__device__ float g_g [ROWS_ * FFN_];

__device__ float g_wq [D_ * D_];
__device__ float g_wk [D_ * D_];
__device__ float g_wv [D_ * D_];
__device__ float g_wo [D_ * D_];
__device__ float g_w1 [D_ * FFN_];
__device__ float g_w2 [D_ * FFN_];
__device__ float g_wout[FFN_ * D_];

// ---------------------------------------------------------------------------
// Helpers
// ---------------------------------------------------------------------------
__device__ __forceinline__ float f2tf32f(float x) {
    unsigned u;
    asm("cvt.rna.tf32.f32 %0, %1;" : "=r"(u) : "f"(x));
    return __uint_as_float(u);
}

__device__ __forceinline__ void mma_tf32(float c[4],
                                         unsigned a0, unsigned a1, unsigned a2, unsigned a3,
                                         unsigned b0, unsigned b1) {
    asm volatile(
        "mma.sync.aligned.m16n8k8.row.col.f32.tf32.tf32.f32 "
        "{%0,%1,%2,%3}, {%4,%5,%6,%7}, {%8,%9}, {%0,%1,%2,%3};"
        : "+f"(c[0]), "+f"(c[1]), "+f"(c[2]), "+f"(c[3])
        : "r"(a0), "r"(a1), "r"(a2), "r"(a3), "r"(b0), "r"(b1));
}

__device__ __forceinline__ void cp16(unsigned dst, const void* src) {
    asm volatile("cp.async.cg.shared.global [%0], [%1], 16;" :: "r"(dst), "l"(src));
}
#define CP_COMMIT() asm volatile("cp.async.commit_group;" ::: "memory")
template <int N> __device__ __forceinline__ void cp_wait() {
    asm volatile("cp.async.wait_group %0;" :: "n"(N) : "memory");
}

// ---------------------------------------------------------------------------
// tf32-round a buffer (weights)
// ---------------------------------------------------------------------------
__global__ void round_kernel(const float* __restrict__ in, float* __restrict__ out)
{
    int i = blockIdx.x * blockDim.x + threadIdx.x;
    float4 v = reinterpret_cast<const float4*>(in)[i];
    v.x = f2tf32f(v.x); v.y = f2tf32f(v.y);
    v.z = f2tf32f(v.z); v.w = f2tf32f(v.w);
    reinterpret_cast<float4*>(out)[i] = v;
}

// ---------------------------------------------------------------------------
// LayerNorm (output tf32-rounded)
// ---------------------------------------------------------------------------
__global__ void ln_kernel(const float* __restrict__ in,
                          const float* __restrict__ gam,
                          const float* __restrict__ bet,
                          float* __restrict__ out)
{
    __shared__ float r1[8], r2[8];
    __shared__ float s_mu, s_rstd;
    int row = blockIdx.x, tid = threadIdx.x;

    const float4* p = reinterpret_cast<const float4*>(in) + (size_t)row * (D_ / 4);
    float4 v = p[tid];
    float s  = v.x + v.y + v.z + v.w;
    float s2 = v.x * v.x + v.y * v.y + v.z * v.z + v.w * v.w;
    #pragma unroll
    for (int o = 16; o; o >>= 1) {
        s  += __shfl_xor_sync(0xffffffffu, s,  o);
        s2 += __shfl_xor_sync(0xffffffffu, s2, o);
    }
    if ((tid & 31) == 0) { r1[tid >> 5] = s; r2[tid >> 5] = s2; }
    __syncthreads();
    if (tid == 0) {
        float a = 0.f, b = 0.f;
        #pragma unroll
        for (int i = 0; i < 8; i++) { a += r1[i]; b += r2[i]; }
        float mu  = a / (float)D_;
        float var = b / (float)D_ - mu * mu;
        s_mu = mu;
        s_rstd = rsqrtf(var + 1e-5f);
    }
    __syncthreads();
    float mu = s_mu, rs = s_rstd;
    float4 g4 = reinterpret_cast<const float4*>(gam)[tid];
    float4 b4 = reinterpret_cast<const float4*>(bet)[tid];
    float4 o;
    o.x = f2tf32f((v.x - mu) * rs * g4.x + b4.x);
    o.y = f2tf32f((v.y - mu) * rs * g4.y + b4.y);
    o.z = f2tf32f((v.z - mu) * rs * g4.z + b4.z);
    o.w = f2tf32f((v.w - mu) * rs * g4.w + b4.w);
    reinterpret_cast<float4*>(out)[(size_t)row * (D_ / 4) + tid] = o;
}

// ---------------------------------------------------------------------------
// TF32 GEMM (round-5 config): 128x128 tile, BK=16, 3-stage cp.async,
// 8 warps (4m x 2n), warp tile 32x64. ROUND: tf32-round outputs.
// ---------------------------------------------------------------------------
#define AST_ 20
#define BST_ 136
#define ATILE_ (128 * AST_)
#define BTILE_ (16 * BST_)
#define GEMM_SMEM (3 * (ATILE_ + BTILE_) * 4)

template <bool RES, bool ROUND, int NGEM>
__global__ void __launch_bounds__(256, 2)
tgemm_kernel(const float* __restrict__ A,
             const float* __restrict__ W0, const float* __restrict__ W1,
             const float* __restrict__ W2,
             const float* __restrict__ R,
             float* __restrict__ C0, float* __restrict__ C1, float* __restrict__ C2,
             int M, int N, int K)
{
    extern __shared__ float sm[];
    float* As = sm;
    float* Bs = sm + 3 * ATILE_;

    const float* W = W0;
    float* C = C0;
    if (NGEM >= 2) {
        int z = blockIdx.z;
        W = (z == 0) ? W0 : (z == 1) ? W1 : W2;
        C = (z == 0) ? C0 : (z == 1) ? C1 : C2;
    }

    const int tid  = threadIdx.x;
    const int lane = tid & 31;
    const int warp = tid >> 5;
    const int wm   = (warp >> 1) * 32;
    const int wn   = (warp & 1) * 64;
    const int qm   = lane >> 2;
    const int qk   = lane & 3;

    const int bm = blockIdx.y * 128, bn = blockIdx.x * 128;

    const int arow0 = tid >> 2;
    const int aseg  = (tid & 3) * 4;
    const int brow0 = tid >> 5;
    const int bseg  = (tid & 31) * 4;

    const float* Abase = A + (size_t)bm * K;
    const float* Wbase = W + bn;

    float acc[2][8][4];
    #pragma unroll
    for (int i = 0; i < 2; i++)
        #pragma unroll
        for (int j = 0; j < 8; j++)
            #pragma unroll
            for (int r = 0; r < 4; r++) acc[i][j][r] = 0.f;

    auto issue_tile = [&](int kt, int st) {
        unsigned abase = (unsigned)__cvta_generic_to_shared(&As[st * ATILE_]);
        unsigned bbase = (unsigned)__cvta_generic_to_shared(&Bs[st * BTILE_]);
        const float* Ag = Abase + kt * 16;
        const float* Bg = Wbase + (size_t)(kt * 16) * N;
        cp16(abase + (unsigned)(arow0 * AST_ + aseg) * 4,
             Ag + (size_t)arow0 * K + aseg);
        cp16(abase + (unsigned)((arow0 + 64) * AST_ + aseg) * 4,
             Ag + (size_t)(arow0 + 64) * K + aseg);
        cp16(bbase + (unsigned)(brow0 * BST_ + bseg) * 4,
             Bg + (size_t)brow0 * N + bseg);
        cp16(bbase + (unsigned)((brow0 + 8) * BST_ + bseg) * 4,
             Bg + (size_t)(brow0 + 8) * N + bseg);
        CP_COMMIT();
    };

    const int ntiles = K / 16;

    issue_tile(0, 0);
    issue_tile(1, 1);
    cp_wait<1>();
    __syncthreads();

    for (int it = 0; it < ntiles; it++) {
        const int s = it % 3;
        if (it + 2 < ntiles) issue_tile(it + 2, (it + 2) % 3);

        const float* Asb = &As[s * ATILE_];
        const float* Bsb = &Bs[s * BTILE_];

        #pragma unroll
        for (int kt = 0; kt < 2; kt++) {
            const int ksb = kt * 8;
            unsigned af[2][4];
            #pragma unroll
            for (int mf = 0; mf < 2; mf++) {
                int m = wm + mf * 16 + qm;
                af[mf][0] = __float_as_uint(Asb[(size_t)m * AST_ + ksb + qk]);
                af[mf][1] = __float_as_uint(Asb[(size_t)(m + 8) * AST_ + ksb + qk]);
                af[mf][2] = __float_as_uint(Asb[(size_t)m * AST_ + ksb + qk + 4]);
                af[mf][3] = __float_as_uint(Asb[(size_t)(m + 8) * AST_ + ksb + qk + 4]);
            }
            unsigned bf[8][2];
            #pragma unroll
            for (int nf = 0; nf < 8; nf++) {
                int n = wn + nf * 8 + qm;
                bf[nf][0] = __float_as_uint(Bsb[(size_t)(ksb + qk) * BST_ + n]);
                bf[nf][1] = __float_as_uint(Bsb[(size_t)(ksb + qk + 4) * BST_ + n]);
            }
            #pragma unroll
            for (int mf = 0; mf < 2; mf++)
                #pragma unroll
                for (int nf = 0; nf < 8; nf++)
                    mma_tf32(acc[mf][nf], af[mf][0], af[mf][1], af[mf][2], af[mf][3],
                             bf[nf][0], bf[nf][1]);
        }

        if (it + 2 < ntiles)       cp_wait<1>();
        else if (it + 1 < ntiles)  cp_wait<0>();
        __syncthreads();
    }

    #pragma unroll
    for (int mf = 0; mf < 2; mf++) {
        int row0 = bm + wm + mf * 16 + qm;
        #pragma unroll
        for (int nf = 0; nf < 8; nf++) {
            int col = bn + wn + nf * 8 + 2 * qk;
            size_t off0 = (size_t)row0 * N + col;
            size_t off1 = (size_t)(row0 + 8) * N + col;
            float2 o0 = make_float2(acc[mf][nf][0], acc[mf][nf][1]);
            float2 o1 = make_float2(acc[mf][nf][2], acc[mf][nf][3]);
            if (RES) {
                float2 r0 = *reinterpret_cast<const float2*>(R + off0);
                float2 r1 = *reinterpret_cast<const float2*>(R + off1);
                o0.x += r0.x; o0.y += r0.y;
                o1.x += r1.x; o1.y += r1.y;
            }
            if (ROUND) {
                o0.x = f2tf32f(o0.x); o0.y = f2tf32f(o0.y);
                o1.x = f2tf32f(o1.x); o1.y = f2tf32f(o1.y);
            }
            *reinterpret_cast<float2*>(C + off0) = o0;
            *reinterpret_cast<float2*>(C + off1) = o1;
        }
    }
}

// ---------------------------------------------------------------------------
// Flash attention via mma.sync tf32. grid (T/64, B*H), 256 threads.
// 8 warps = 4(m) x 2(n-half); S/P tiles 64x64; online softmax.
// Qs[64][68] [m][d]; Kts[64][72] [d][t]; Vs[64][72] [t][d]; Ps[64][68] [m][t].
// Inputs q,k,v tf32-rounded (GEMM ROUND epilogue). Output tf32-rounded.
// ---------------------------------------------------------------------------
#define QST_ 68
#define KST_ 72
#define ATTN_SMEM ((64 * QST_ + 64 * KST_ + 64 * KST_ + 64 * QST_ + 256) * 4)

__global__ void __launch_bounds__(256)
attn_kernel(const float* __restrict__ Q, const float* __restrict__ K,
            const float* __restrict__ V, float* __restrict__ O)
{
    extern __shared__ float smf[];
    float* Qs    = smf;                      // [64][QST_]
    float* Kts   = Qs  + 64 * QST_;          // [d][t]
    float* Vs    = Kts + 64 * KST_;          // [t][d]
    float* Ps    = Vs  + 64 * KST_;          // [m][t]
    float* redmx = Ps  + 64 * QST_;          // [2][64]
    float* redsm = redmx + 128;              // [2][64]

    const int tid  = threadIdx.x;
    const int lane = tid & 31;
    const int warp = tid >> 5;
    const int wm   = (warp >> 1) * 16;       // warp m-offset (0,16,32,48)
    const int wnh  = warp & 1;               // n half (0/1) -> col offset 32*wnh
    const int qm   = lane >> 2;
    const int qk   = lane & 3;

    const int b = blockIdx.y >> 4, h = blockIdx.y & 15;
    const int qb = blockIdx.x * 64;

    const float* Qb = Q + (size_t)b * T_ * D_ + h * HD_;
    const float* Kb = K + (size_t)b * T_ * D_ + h * HD_;
    const float* Vb = V + (size_t)b * T_ * D_ + h * HD_;

    // load Q tile (once): row=tid>>2, d-seg=(tid&3)*16
    {
        int row = tid >> 2, d0 = (tid & 3) * 16;
        #pragma unroll
        for (int rep = 0; rep < 4; rep++) {
            float4 qv = *reinterpret_cast<const float4*>(
                Qb + (size_t)(qb + row) * D_ + d0 + rep * 4);
            *reinterpret_cast<float4*>(&Qs[row * QST_ + d0 + rep * 4]) = qv;
        }
    }

    float acc[4][4];     // O frags: nf 0..3, c 0..3
    float m_i[2], l_i[2];
    m_i[0] = m_i[1] = -1e30f;
    l_i[0] = l_i[1] = 0.f;
    #pragma unroll
    for (int nf = 0; nf < 4; nf++)
        #pragma unroll
        for (int c = 0; c < 4; c++) acc[nf][c] = 0.f;

    const int r0l = wm + qm;          // local rows r0l, r0l+8
    const int ntile = blockIdx.x + 1;

    for (int j = 0; j < ntile; j++) {
        const int jb = j * 64;
        __syncthreads();   // prior iter done with Kts/Vs/Ps

        // K transposed: row=tid&63 (token), d-base=(tid>>6)*16
        {
            int krow = tid & 63, kd0 = (tid >> 6) * 16;
            #pragma unroll
            for (int rep = 0; rep < 4; rep++) {
                float4 kv = *reinterpret_cast<const float4*>(
                    Kb + (size_t)(jb + krow) * D_ + kd0 + rep * 4);
                int d = kd0 + rep * 4;
                Kts[(d + 0) * KST_ + krow] = kv.x;
                Kts[(d + 1) * KST_ + krow] = kv.y;
                Kts[(d + 2) * KST_ + krow] = kv.z;
                Kts[(d + 3) * KST_ + krow] = kv.w;
            }
        }
        // V straight
        {
            int vrow = tid >> 2, vd0 = (tid & 3) * 16;
            #pragma unroll
            for (int rep = 0; rep < 4; rep++) {
                float4 vv = *reinterpret_cast<const float4*>(
                    Vb + (size_t)(jb + vrow) * D_ + vd0 + rep * 4);
                *reinterpret_cast<float4*>(&Vs[vrow * KST_ + vd0 + rep * 4]) = vv;
            }
        }
        __syncthreads();

        // ---- S = Q @ K^T (warp tile 16 x 32) ----
        float s[4][4];
        #pragma unroll
        for (int nf = 0; nf < 4; nf++)
            #pragma unroll
            for (int c = 0; c < 4; c++) s[nf][c] = 0.f;

        #pragma unroll
        for (int ks = 0; ks < 8; ks++) {
            const int kk = ks * 8;
            unsigned a0 = __float_as_uint(Qs[(size_t)r0l * QST_ + kk + qk]);
            unsigned a1 = __float_as_uint(Qs[(size_t)(r0l + 8) * QST_ + kk + qk]);
            unsigned a2 = __float_as_uint(Qs[(size_t)r0l * QST_ + kk + qk + 4]);
            unsigned a3 = __float_as_uint(Qs[(size_t)(r0l + 8) * QST_ + kk + qk + 4]);
            #pragma unroll
            for (int nf = 0; nf < 4; nf++) {
                int n = wnh * 32 + nf * 8 + qm;
                unsigned b0 = __float_as_uint(Kts[(size_t)(kk + qk) * KST_ + n]);
                unsigned b1 = __float_as_uint(Kts[(size_t)(kk + qk + 4) * KST_ + n]);
                mma_tf32(s[nf], a0, a1, a2, a3, b0, b1);
            }
        }

        // scale + causal mask (diag tile only)
        const bool diag = (jb == qb);
        #pragma unroll
        for (int nf = 0; nf < 4; nf++) {
            int colb = wnh * 32 + nf * 8 + 2 * qk;
            #pragma unroll
            for (int c = 0; c < 4; c++) {
                int col = colb + (c & 1);
                int row = r0l + ((c >> 1) ? 8 : 0);
                float sv = s[nf][c] * 0.125f;
                if (diag && (col > row)) sv = -1e30f;
                s[nf][c] = sv;
            }
        }

        // row max: in-thread over nf, then qk-quad shfl, then 2-half smem combine
        float mx0 = -1e30f, mx1 = -1e30f;
        #pragma unroll
        for (int nf = 0; nf < 4; nf++) {
            mx0 = fmaxf(mx0, fmaxf(s[nf][0], s[nf][1]));
            mx1 = fmaxf(mx1, fmaxf(s[nf][2], s[nf][3]));
        }
        #pragma unroll
        for (int o = 1; o < 4; o <<= 1) {
            mx0 = fmaxf(mx0, __shfl_xor_sync(0xffffffffu, mx0, o));
            mx1 = fmaxf(mx1, __shfl_xor_sync(0xffffffffu, mx1, o));
        }
        if ((lane & 3) == 0) {
            redmx[wnh * 64 + r0l]     = mx0;
            redmx[wnh * 64 + r0l + 8] = mx1;
        }
        __syncthreads();
        float mn0 = fmaxf(m_i[0], fmaxf(redmx[r0l],     redmx[64 + r0l]));
        float mn1 = fmaxf(m_i[1], fmaxf(redmx[r0l + 8], redmx[64 + r0l + 8]));

        // p = exp(s - mn); write tf32(p) to Ps; row sums
        float sum0 = 0.f, sum1 = 0.f;
        #pragma unroll
        for (int nf = 0; nf < 4; nf++) {
            int colb = wnh * 32 + nf * 8 + 2 * qk;
            float p0 = __expf(s[nf][0] - mn0);
            float p1 = __expf(s[nf][1] - mn0);
            float p2 = __expf(s[nf][2] - mn1);
            float p3 = __expf(s[nf][3] - mn1);
            sum0 += p0 + p1;
            sum1 += p2 + p3;
            Ps[(size_t)r0l * QST_ + colb]           = f2tf32f(p0);
            Ps[(size_t)r0l * QST_ + colb + 1]       = f2tf32f(p1);
            Ps[(size_t)(r0l + 8) * QST_ + colb]     = f2tf32f(p2);
            Ps[(size_t)(r0l + 8) * QST_ + colb + 1] = f2tf32f(p3);
        }
        #pragma unroll
        for (int o = 1; o < 4; o <<= 1) {
            sum0 += __shfl_xor_sync(0xffffffffu, sum0, o);
            sum1 += __shfl_xor_sync(0xffffffffu, sum1, o);
        }
        if ((lane & 3) == 0) {
            redsm[wnh * 64 + r0l]     = sum0;
            redsm[wnh * 64 + r0l + 8] = sum1;
        }
        __syncthreads();
        float ts0 = redsm[r0l]     + redsm[64 + r0l];
        float ts1 = redsm[r0l + 8] + redsm[64 + r0l + 8];

        float al0 = __expf(m_i[0] - mn0);
        float al1 = __expf(m_i[1] - mn1);
        l_i[0] = l_i[0] * al0 + ts0;  m_i[0] = mn0;
        l_i[1] = l_i[1] * al1 + ts1;  m_i[1] = mn1;
        #pragma unroll
        for (int nf = 0; nf < 4; nf++) {
            acc[nf][0] *= al0; acc[nf][1] *= al0;
            acc[nf][2] *= al1; acc[nf][3] *= al1;
        }

        // ---- O += P @ V (warp tile 16 x 32 over head dims) ----
        #pragma unroll
        for (int ks = 0; ks < 8; ks++) {
            const int kk = ks * 8;
            unsigned a0 = __float_as_uint(Ps[(size_t)r0l * QST_ + kk + qk]);
            unsigned a1 = __float_as_uint(Ps[(size_t)(r0l + 8) * QST_ + kk + qk]);
            unsigned a2 = __float_as_uint(Ps[(size_t)r0l * QST_ + kk + qk + 4]);
            unsigned a3 = __float_as_uint(Ps[(size_t)(r0l + 8) * QST_ + kk + qk + 4]);
            #pragma unroll
            for (int nf = 0; nf < 4; nf++) {
                int n = wnh * 32 + nf * 8 + qm;
                unsigned b0 = __float_as_uint(Vs[(size_t)(kk + qk) * KST_ + n]);
                unsigned b1 = __float_as_uint(Vs[(size_t)(kk + qk + 4) * KST_ + n]);
                mma_tf32(acc[nf], a0, a1, a2, a3, b0, b1);
            }
        }
    }

    // epilogue: O rows qb+r0l(+8), cols h*HD + wnh*32 + nf*8 + 2qk(+1)
    {
        float inv0 = 1.0f / l_i[0], inv1 = 1.0f / l_i[1];
        #pragma unroll
        for (int nf = 0; nf < 4; nf++) {
            int col = h * HD_ + wnh * 32 + nf * 8 + 2 * qk;
            size_t off0 = (size_t)b * T_ * D_ + (size_t)(qb + r0l) * D_ + col;
            size_t off1 = (size_t)b * T_ * D_ + (size_t)(qb + r0l + 8) * D_ + col;
            float2 o0 = make_float2(f2tf32f(acc[nf][0] * inv0), f2tf32f(acc[nf][1] * inv0));
            float2 o1 = make_float2(f2tf32f(acc[nf][2] * inv1), f2tf32f(acc[nf][3] * inv1));
            *reinterpret_cast<float2*>(const_cast<float*>(O) + off0) = o0;
            *reinterpret_cast<float2*>(const_cast<float*>(O) + off1) = o1;
        }
    }
}

// ---------------------------------------------------------------------------
// a = tf32(silu(a) * g)
// ---------------------------------------------------------------------------
__global__ void silu_mul_kernel(float* __restrict__ a, const float* __restrict__ g)
{
    int i = blockIdx.x * blockDim.x + threadIdx.x;
    float4 av = reinterpret_cast<float4*>(a)[i];
    float4 gv = reinterpret_cast<const float4*>(g)[i];
    av.x = f2tf32f(av.x / (1.f + __expf(-av.x)) * gv.x);
    av.y = f2tf32f(av.y / (1.f + __expf(-av.y)) * gv.y);
    av.z = f2tf32f(av.z / (1.f + __expf(-av.z)) * gv.z);
    av.w = f2tf32f(av.w / (1.f + __expf(-av.w)) * gv.w);
    reinterpret_cast<float4*>(a)[i] = av;
}

// ---------------------------------------------------------------------------
// Orchestration
// ---------------------------------------------------------------------------
extern "C" void kernel_launch(void* const* d_in, const int* in_sizes, int n_in,
                              void* d_out, int out_size)
{
    const float* h    = (const float*)d_in[0];
    const float* alng = (const float*)d_in[2];
    const float* alnb = (const float*)d_in[3];
    const float* mlng = (const float*)d_in[4];
    const float* mlnb = (const float*)d_in[5];
    const float* wq   = (const float*)d_in[6];
    const float* wk   = (const float*)d_in[7];
    const float* wv   = (const float*)d_in[8];
    const float* wo   = (const float*)d_in[9];
    const float* w1   = (const float*)d_in[10];
    const float* w2   = (const float*)d_in[11];
    const float* wout = (const float*)d_in[12];
    float* out = (float*)d_out;

    float *px, *pq, *pk, *pv, *po, *ph2, *py, *pa, *pg;
    float *rwq, *rwk, *rwv, *rwo, *rw1, *rw2, *rwout;
    cudaGetSymbolAddress((void**)&px,  g_x);
    cudaGetSymbolAddress((void**)&pq,  g_q);
    cudaGetSymbolAddress((void**)&pk,  g_k);
    cudaGetSymbolAddress((void**)&pv,  g_v);
    cudaGetSymbolAddress((void**)&po,  g_o);
    cudaGetSymbolAddress((void**)&ph2, g_h2);
    cudaGetSymbolAddress((void**)&py,  g_y);
    cudaGetSymbolAddress((void**)&pa,  g_a);
    cudaGetSymbolAddress((void**)&pg,  g_g);
    cudaGetSymbolAddress((void**)&rwq,   g_wq);
    cudaGetSymbolAddress((void**)&rwk,   g_wk);
    cudaGetSymbolAddress((void**)&rwv,   g_wv);
    cudaGetSymbolAddress((void**)&rwo,   g_wo);
    cudaGetSymbolAddress((void**)&rw1,   g_w1);
    cudaGetSymbolAddress((void**)&rw2,   g_w2);
    cudaGetSymbolAddress((void**)&rwout, g_wout);

    cudaFuncSetAttribute(attn_kernel, cudaFuncAttributeMaxDynamicSharedMemorySize, ATTN_SMEM);
    cudaFuncSetAttribute(tgemm_kernel<false, true, 3>,  cudaFuncAttributeMaxDynamicSharedMemorySize, GEMM_SMEM);
    cudaFuncSetAttribute(tgemm_kernel<false, false, 2>, cudaFuncAttributeMaxDynamicSharedMemorySize, GEMM_SMEM);
    cudaFuncSetAttribute(tgemm_kernel<true, false, 1>,  cudaFuncAttributeMaxDynamicSharedMemorySize, GEMM_SMEM);

    // tf32-round weights
    round_kernel<<<(D_ * D_ / 4) / 256, 256>>>(wq, rwq);
    round_kernel<<<(D_ * D_ / 4) / 256, 256>>>(wk, rwk);
    round_kernel<<<(D_ * D_ / 4) / 256, 256>>>(wv, rwv);
    round_kernel<<<(D_ * D_ / 4) / 256, 256>>>(wo, rwo);
    round_kernel<<<(D_ * FFN_ / 4) / 256, 256>>>(w1, rw1);
    round_kernel<<<(D_ * FFN_ / 4) / 256, 256>>>(w2, rw2);
    round_kernel<<<(FFN_ * D_ / 4) / 256, 256>>>(wout, rwout);

    dim3 gQKV(D_ / 128, ROWS_ / 128, 3);   // (8, 64, 3)
    dim3 gD(D_ / 128, ROWS_ / 128);        // (8, 64)
    dim3 gFF(FFN_ / 128, ROWS_ / 128, 2);  // (32, 64, 2)

    // x = tf32(LN(h))
    ln_kernel<<<ROWS_, 256>>>(h, alng, alnb, px);
    // q,k,v = tf32(x @ {wq,wk,wv})  (fused; ROUND so attention MMAs get tf32 bits)
    tgemm_kernel<false, true, 3><<<gQKV, 256, GEMM_SMEM>>>(px, rwq, rwk, rwv, nullptr,
                                                           pq, pk, pv, ROWS_, D_, D_);
    // o = tf32(attention(q,k,v))  (tensor-core attention)
    attn_kernel<<<dim3(T_ / 64, B_ * H_), 256, ATTN_SMEM>>>(pq, pk, pv, po);
    // h2 = h + o @ wo
    tgemm_kernel<true, false, 1><<<gD, 256, GEMM_SMEM>>>(po, rwo, nullptr, nullptr, h,
                                                         ph2, nullptr, nullptr, ROWS_, D_, D_);
    // y = tf32(LN(h2))
    ln_kernel<<<ROWS_, 256>>>(ph2, mlng, mlnb, py);
    // a = y@w1 ; g = y@w2  (fused)
    tgemm_kernel<false, false, 2><<<gFF, 256, GEMM_SMEM>>>(py, rw1, rw2, nullptr, nullptr,
                                                           pa, pg, nullptr, ROWS_, FFN_, D_);
    // a = tf32(silu(a)*g)
    silu_mul_kernel<<<(ROWS_ * FFN_ / 4) / 256, 256>>>(pa, pg);
    // out = h2 + a @ wout
    tgemm_kernel<true, false, 1><<<gD, 256, GEMM_SMEM>>>(pa, rwout, nullptr, nullptr, ph2,
                                                         out, nullptr, nullptr, ROWS_, D_, FFN_);
}

// round 9
// speedup vs baseline: 1.3216x; 1.0851x over previous
#include <cuda_runtime.h>
#include <math.h>

// Problem constants
#define B_    4
#define T_    2048
#define D_    1024
#define H_    16
#define HD_   64
#define FFN_  4096
#define ROWS_ (B_ * T_)        // 8192

// ---------------------------------------------------------------------------
// Scratch (device globals)
// ---------------------------------------------------------------------------
__device__ float g_x [ROWS_ * D_];
__device__ float g_q [ROWS_ * D_];
__device__ float g_k [ROWS_ * D_];
__device__ float g_v [ROWS_ * D_];
__device__ float g_o [ROWS_ * D_];
__device__ float g_h2[ROWS_ * D_];
__device__ float g_y [ROWS_ * D_];
__device__ float g_a [ROWS_ * FFN_];   // fused FFN output: tf32(silu(y@w1)*(y@w2))

__device__ float g_wq [D_ * D_];
__device__ float g_wk [D_ * D_];
__device__ float g_wv [D_ * D_];
__device__ float g_wo [D_ * D_];
__device__ float g_w1 [D_ * FFN_];
__device__ float g_w2 [D_ * FFN_];
__device__ float g_wout[FFN_ * D_];

// ---------------------------------------------------------------------------
// Helpers
// ---------------------------------------------------------------------------
__device__ __forceinline__ float f2tf32f(float x) {
    unsigned u;
    asm("cvt.rna.tf32.f32 %0, %1;" : "=r"(u) : "f"(x));
    return __uint_as_float(u);
}

__device__ __forceinline__ void mma_tf32(float c[4],
                                         unsigned a0, unsigned a1, unsigned a2, unsigned a3,
                                         unsigned b0, unsigned b1) {
    asm volatile(
        "mma.sync.aligned.m16n8k8.row.col.f32.tf32.tf32.f32 "
        "{%0,%1,%2,%3}, {%4,%5,%6,%7}, {%8,%9}, {%0,%1,%2,%3};"
        : "+f"(c[0]), "+f"(c[1]), "+f"(c[2]), "+f"(c[3])
        : "r"(a0), "r"(a1), "r"(a2), "r"(a3), "r"(b0), "r"(b1));
}

__device__ __forceinline__ void cp16(unsigned dst, const void* src) {
    asm volatile("cp.async.cg.shared.global [%0], [%1], 16;" :: "r"(dst), "l"(src));
}
#define CP_COMMIT() asm volatile("cp.async.commit_group;" ::: "memory")
template <int N> __device__ __forceinline__ void cp_wait() {
    asm volatile("cp.async.wait_group %0;" :: "n"(N) : "memory");
}

// ---------------------------------------------------------------------------
// tf32-round a buffer (weights)
// ---------------------------------------------------------------------------
__global__ void round_kernel(const float* __restrict__ in, float* __restrict__ out)
{
    int i = blockIdx.x * blockDim.x + threadIdx.x;
    float4 v = reinterpret_cast<const float4*>(in)[i];
    v.x = f2tf32f(v.x); v.y = f2tf32f(v.y);
    v.z = f2tf32f(v.z); v.w = f2tf32f(v.w);
    reinterpret_cast<float4*>(out)[i] = v;
}

// ---------------------------------------------------------------------------
// LayerNorm (output tf32-rounded)
// ---------------------------------------------------------------------------
__global__ void ln_kernel(const float* __restrict__ in,
                          const float* __restrict__ gam,
                          const float* __restrict__ bet,
                          float* __restrict__ out)
{
    __shared__ float r1[8], r2[8];
    __shared__ float s_mu, s_rstd;
    int row = blockIdx.x, tid = threadIdx.x;

    const float4* p = reinterpret_cast<const float4*>(in) + (size_t)row * (D_ / 4);
    float4 v = p[tid];
    float s  = v.x + v.y + v.z + v.w;
    float s2 = v.x * v.x + v.y * v.y + v.z * v.z + v.w * v.w;
    #pragma unroll
    for (int o = 16; o; o >>= 1) {
        s  += __shfl_xor_sync(0xffffffffu, s,  o);
        s2 += __shfl_xor_sync(0xffffffffu, s2, o);
    }
    if ((tid & 31) == 0) { r1[tid >> 5] = s; r2[tid >> 5] = s2; }
    __syncthreads();
    if (tid == 0) {
        float a = 0.f, b = 0.f;
        #pragma unroll
        for (int i = 0; i < 8; i++) { a += r1[i]; b += r2[i]; }
        float mu  = a / (float)D_;
        float var = b / (float)D_ - mu * mu;
        s_mu = mu;
        s_rstd = rsqrtf(var + 1e-5f);
    }
    __syncthreads();
    float mu = s_mu, rs = s_rstd;
    float4 g4 = reinterpret_cast<const float4*>(gam)[tid];
    float4 b4 = reinterpret_cast<const float4*>(bet)[tid];
    float4 o;
    o.x = f2tf32f((v.x - mu) * rs * g4.x + b4.x);
    o.y = f2tf32f((v.y - mu) * rs * g4.y + b4.y);
    o.z = f2tf32f((v.z - mu) * rs * g4.z + b4.z);
    o.w = f2tf32f((v.w - mu) * rs * g4.w + b4.w);
    reinterpret_cast<float4*>(out)[(size_t)row * (D_ / 4) + tid] = o;
}

// ---------------------------------------------------------------------------
// TF32 GEMM: 128x128 tile, BK=16, 3-stage cp.async, 8 warps (4m x 2n),
// warp tile 32x64. ROUND: tf32-round outputs. NGEM: z selects W/C.
// ---------------------------------------------------------------------------
#define AST_ 20
#define BST_ 136
#define ATILE_ (128 * AST_)
#define BTILE_ (16 * BST_)
#define GEMM_SMEM (3 * (ATILE_ + BTILE_) * 4)

template <bool RES, bool ROUND, int NGEM>
__global__ void __launch_bounds__(256, 2)
tgemm_kernel(const float* __restrict__ A,
             const float* __restrict__ W0, const float* __restrict__ W1,
             const float* __restrict__ W2,
             const float* __restrict__ R,
             float* __restrict__ C0, float* __restrict__ C1, float* __restrict__ C2,
             int M, int N, int K)
{
    extern __shared__ float sm[];
    float* As = sm;
    float* Bs = sm + 3 * ATILE_;

    const float* W = W0;
    float* C = C0;
    if (NGEM >= 2) {
        int z = blockIdx.z;
        W = (z == 0) ? W0 : (z == 1) ? W1 : W2;
        C = (z == 0) ? C0 : (z == 1) ? C1 : C2;
    }

    const int tid  = threadIdx.x;
    const int lane = tid & 31;
    const int warp = tid >> 5;
    const int wm   = (warp >> 1) * 32;
    const int wn   = (warp & 1) * 64;
    const int qm   = lane >> 2;
    const int qk   = lane & 3;

    const int bm = blockIdx.y * 128, bn = blockIdx.x * 128;

    const int arow0 = tid >> 2;
    const int aseg  = (tid & 3) * 4;
    const int brow0 = tid >> 5;
    const int bseg  = (tid & 31) * 4;

    const float* Abase = A + (size_t)bm * K;
    const float* Wbase = W + bn;

    float acc[2][8][4];
    #pragma unroll
    for (int i = 0; i < 2; i++)
        #pragma unroll
        for (int j = 0; j < 8; j++)
            #pragma unroll
            for (int r = 0; r < 4; r++) acc[i][j][r] = 0.f;

    auto issue_tile = [&](int kt, int st) {
        unsigned abase = (unsigned)__cvta_generic_to_shared(&As[st * ATILE_]);
        unsigned bbase = (unsigned)__cvta_generic_to_shared(&Bs[st * BTILE_]);
        const float* Ag = Abase + kt * 16;
        const float* Bg = Wbase + (size_t)(kt * 16) * N;
        cp16(abase + (unsigned)(arow0 * AST_ + aseg) * 4,
             Ag + (size_t)arow0 * K + aseg);
        cp16(abase + (unsigned)((arow0 + 64) * AST_ + aseg) * 4,
             Ag + (size_t)(arow0 + 64) * K + aseg);
        cp16(bbase + (unsigned)(brow0 * BST_ + bseg) * 4,
             Bg + (size_t)brow0 * N + bseg);
        cp16(bbase + (unsigned)((brow0 + 8) * BST_ + bseg) * 4,
             Bg + (size_t)(brow0 + 8) * N + bseg);
        CP_COMMIT();
    };

    const int ntiles = K / 16;

    issue_tile(0, 0);
    issue_tile(1, 1);
    cp_wait<1>();
    __syncthreads();

    for (int it = 0; it < ntiles; it++) {
        const int s = it % 3;
        if (it + 2 < ntiles) issue_tile(it + 2, (it + 2) % 3);

        const float* Asb = &As[s * ATILE_];
        const float* Bsb = &Bs[s * BTILE_];

        #pragma unroll
        for (int kt = 0; kt < 2; kt++) {
            const int ksb = kt * 8;
            unsigned af[2][4];
            #pragma unroll
            for (int mf = 0; mf < 2; mf++) {
                int m = wm + mf * 16 + qm;
                af[mf][0] = __float_as_uint(Asb[(size_t)m * AST_ + ksb + qk]);
                af[mf][1] = __float_as_uint(Asb[(size_t)(m + 8) * AST_ + ksb + qk]);
                af[mf][2] = __float_as_uint(Asb[(size_t)m * AST_ + ksb + qk + 4]);
                af[mf][3] = __float_as_uint(Asb[(size_t)(m + 8) * AST_ + ksb + qk + 4]);
            }
            unsigned bf[8][2];
            #pragma unroll
            for (int nf = 0; nf < 8; nf++) {
                int n = wn + nf * 8 + qm;
                bf[nf][0] = __float_as_uint(Bsb[(size_t)(ksb + qk) * BST_ + n]);
                bf[nf][1] = __float_as_uint(Bsb[(size_t)(ksb + qk + 4) * BST_ + n]);
            }
            #pragma unroll
            for (int mf = 0; mf < 2; mf++)
                #pragma unroll
                for (int nf = 0; nf < 8; nf++)
                    mma_tf32(acc[mf][nf], af[mf][0], af[mf][1], af[mf][2], af[mf][3],
                             bf[nf][0], bf[nf][1]);
        }

        if (it + 2 < ntiles)       cp_wait<1>();
        else if (it + 1 < ntiles)  cp_wait<0>();
        __syncthreads();
    }

    #pragma unroll
    for (int mf = 0; mf < 2; mf++) {
        int row0 = bm + wm + mf * 16 + qm;
        #pragma unroll
        for (int nf = 0; nf < 8; nf++) {
            int col = bn + wn + nf * 8 + 2 * qk;
            size_t off0 = (size_t)row0 * N + col;
            size_t off1 = (size_t)(row0 + 8) * N + col;
            float2 o0 = make_float2(acc[mf][nf][0], acc[mf][nf][1]);
            float2 o1 = make_float2(acc[mf][nf][2], acc[mf][nf][3]);
            if (RES) {
                float2 r0 = *reinterpret_cast<const float2*>(R + off0);
                float2 r1 = *reinterpret_cast<const float2*>(R + off1);
                o0.x += r0.x; o0.y += r0.y;
                o1.x += r1.x; o1.y += r1.y;
            }
            if (ROUND) {
                o0.x = f2tf32f(o0.x); o0.y = f2tf32f(o0.y);
                o1.x = f2tf32f(o1.x); o1.y = f2tf32f(o1.y);
            }
            *reinterpret_cast<float2*>(C + off0) = o0;
            *reinterpret_cast<float2*>(C + off1) = o1;
        }
    }
}

// ---------------------------------------------------------------------------
// Fused FFN: C = tf32(silu(A@W1) * (A@W2)). Block tile 128m x 64n (per matrix),
// 8 warps (4m x 2n), warp tile 32x32 per matrix, dual accumulators.
// Bs layout: cols 0..63 = W1 tile, 64..127 = W2 tile (stride 136).
// ---------------------------------------------------------------------------
__global__ void __launch_bounds__(256, 2)
ffn_kernel(const float* __restrict__ A,
           const float* __restrict__ W1, const float* __restrict__ W2,
           float* __restrict__ C, int M, int N, int K)
{
    extern __shared__ float sm[];
    float* As = sm;
    float* Bs = sm + 3 * ATILE_;

    const int tid  = threadIdx.x;
    const int lane = tid & 31;
    const int warp = tid >> 5;
    const int wm   = (warp >> 1) * 32;   // 0,32,64,96
    const int wn   = (warp & 1) * 32;    // 0,32 (within 64-col half)
    const int qm   = lane >> 2;
    const int qk   = lane & 3;

    const int bm = blockIdx.y * 128, bn = blockIdx.x * 64;

    const int arow0 = tid >> 2;
    const int aseg  = (tid & 3) * 4;
    const int brow0 = tid >> 5;          // 0..7 (+8)
    const int bseg  = (tid & 31) * 4;    // 0..124

    const float* Abase = A + (size_t)bm * K;
    // per-thread B source base: cols <64 from W1, else W2 (same global cols bn..bn+63)
    const float* WB = (bseg < 64) ? (W1 + bn + bseg) : (W2 + bn + bseg - 64);

    float acc1[2][4][4], acc2[2][4][4];
    #pragma unroll
    for (int i = 0; i < 2; i++)
        #pragma unroll
        for (int j = 0; j < 4; j++)
            #pragma unroll
            for (int r = 0; r < 4; r++) { acc1[i][j][r] = 0.f; acc2[i][j][r] = 0.f; }

    auto issue_tile = [&](int kt, int st) {
        unsigned abase = (unsigned)__cvta_generic_to_shared(&As[st * ATILE_]);
        unsigned bbase = (unsigned)__cvta_generic_to_shared(&Bs[st * BTILE_]);
        const float* Ag = Abase + kt * 16;
        const float* Bg = WB + (size_t)(kt * 16) * N;
        cp16(abase + (unsigned)(arow0 * AST_ + aseg) * 4,
             Ag + (size_t)arow0 * K + aseg);
        cp16(abase + (unsigned)((arow0 + 64) * AST_ + aseg) * 4,
             Ag + (size_t)(arow0 + 64) * K + aseg);
        cp16(bbase + (unsigned)(brow0 * BST_ + bseg) * 4,
             Bg + (size_t)brow0 * N);
        cp16(bbase + (unsigned)((brow0 + 8) * BST_ + bseg) * 4,
             Bg + (size_t)(brow0 + 8) * N);
        CP_COMMIT();
    };

    const int ntiles = K / 16;

    issue_tile(0, 0);
    issue_tile(1, 1);
    cp_wait<1>();
    __syncthreads();

    for (int it = 0; it < ntiles; it++) {
        const int s = it % 3;
        if (it + 2 < ntiles) issue_tile(it + 2, (it + 2) % 3);

        const float* Asb = &As[s * ATILE_];
        const float* Bsb = &Bs[s * BTILE_];

        #pragma unroll
        for (int kt = 0; kt < 2; kt++) {
            const int ksb = kt * 8;
            unsigned af[2][4];
            #pragma unroll
            for (int mf = 0; mf < 2; mf++) {
                int m = wm + mf * 16 + qm;
                af[mf][0] = __float_as_uint(Asb[(size_t)m * AST_ + ksb + qk]);
                af[mf][1] = __float_as_uint(Asb[(size_t)(m + 8) * AST_ + ksb + qk]);
                af[mf][2] = __float_as_uint(Asb[(size_t)m * AST_ + ksb + qk + 4]);
                af[mf][3] = __float_as_uint(Asb[(size_t)(m + 8) * AST_ + ksb + qk + 4]);
            }
            unsigned bf1[4][2], bf2[4][2];
            #pragma unroll
            for (int nf = 0; nf < 4; nf++) {
                int n = wn + nf * 8 + qm;
                bf1[nf][0] = __float_as_uint(Bsb[(size_t)(ksb + qk) * BST_ + n]);
                bf1[nf][1] = __float_as_uint(Bsb[(size_t)(ksb + qk + 4) * BST_ + n]);
                bf2[nf][0] = __float_as_uint(Bsb[(size_t)(ksb + qk) * BST_ + n + 64]);
                bf2[nf][1] = __float_as_uint(Bsb[(size_t)(ksb + qk + 4) * BST_ + n + 64]);
            }
            #pragma unroll
            for (int mf = 0; mf < 2; mf++)
                #pragma unroll
                for (int nf = 0; nf < 4; nf++) {
                    mma_tf32(acc1[mf][nf], af[mf][0], af[mf][1], af[mf][2], af[mf][3],
                             bf1[nf][0], bf1[nf][1]);
                    mma_tf32(acc2[mf][nf], af[mf][0], af[mf][1], af[mf][2], af[mf][3],
                             bf2[nf][0], bf2[nf][1]);
                }
        }

        if (it + 2 < ntiles)       cp_wait<1>();
        else if (it + 1 < ntiles)  cp_wait<0>();
        __syncthreads();
    }

    // epilogue: o = tf32(silu(a) * g)
    #pragma unroll
    for (int mf = 0; mf < 2; mf++) {
        int row0 = bm + wm + mf * 16 + qm;
        #pragma unroll
        for (int nf = 0; nf < 4; nf++) {
            int col = bn + wn + nf * 8 + 2 * qk;
            size_t off0 = (size_t)row0 * N + col;
            size_t off1 = (size_t)(row0 + 8) * N + col;
            float a0 = acc1[mf][nf][0], a1 = acc1[mf][nf][1];
            float a2 = acc1[mf][nf][2], a3 = acc1[mf][nf][3];
            float g0 = acc2[mf][nf][0], g1 = acc2[mf][nf][1];
            float g2 = acc2[mf][nf][2], g3 = acc2[mf][nf][3];
            float2 o0, o1;
            o0.x = f2tf32f(a0 / (1.f + __expf(-a0)) * g0);
            o0.y = f2tf32f(a1 / (1.f + __expf(-a1)) * g1);
            o1.x = f2tf32f(a2 / (1.f + __expf(-a2)) * g2);
            o1.y = f2tf32f(a3 / (1.f + __expf(-a3)) * g3);
            *reinterpret_cast<float2*>(C + off0) = o0;
            *reinterpret_cast<float2*>(C + off1) = o1;
        }
    }
}

// ---------------------------------------------------------------------------
// Flash attention via mma.sync tf32, cp.async K/V double buffer.
// grid (T/64, B*H), 256 threads. 8 warps = 4(m) x 2(n-half).
// Qs/Ks natural [t][d] stride 68; Vs natural [t][d] stride 72; Ps [m][t] 68.
// ---------------------------------------------------------------------------
#define QST_ 68
#define VST_ 72
#define ATTN_SMEM ((64 * QST_ + 2 * 64 * QST_ + 2 * 64 * VST_ + 64 * QST_ + 256) * 4)

__global__ void __launch_bounds__(256)
attn_kernel(const float* __restrict__ Q, const float* __restrict__ K,
            const float* __restrict__ V, float* __restrict__ O)
{
    extern __shared__ float smf[];
    float* Qs    = smf;                       // [64][QST_]
    float* Ks    = Qs  + 64 * QST_;           // [2][64][QST_]  natural [t][d]
    float* Vs    = Ks  + 2 * 64 * QST_;       // [2][64][VST_]  natural [t][d]
    float* Ps    = Vs  + 2 * 64 * VST_;       // [m][t]
    float* redmx = Ps  + 64 * QST_;           // [2][64]
    float* redsm = redmx + 128;               // [2][64]

    const int tid  = threadIdx.x;
    const int lane = tid & 31;
    const int warp = tid >> 5;
    const int wm   = (warp >> 1) * 16;        // 0,16,32,48
    const int wnh  = warp & 1;                // col offset 32*wnh
    const int qm   = lane >> 2;
    const int qk   = lane & 3;

    const int b = blockIdx.y >> 4, h = blockIdx.y & 15;
    const int qb = blockIdx.x * 64;

    const float* Qb = Q + (size_t)b * T_ * D_ + h * HD_;
    const float* Kb = K + (size_t)b * T_ * D_ + h * HD_;
    const float* Vb = V + (size_t)b * T_ * D_ + h * HD_;

    const int lrow = tid >> 2, ld0 = (tid & 3) * 16;   // loader coords

    auto issue_kv = [&](int j, int s) {
        unsigned kb_ = (unsigned)__cvta_generic_to_shared(&Ks[s * 64 * QST_]);
        unsigned vb_ = (unsigned)__cvta_generic_to_shared(&Vs[s * 64 * VST_]);
        const float* Kg = Kb + (size_t)(j * 64 + lrow) * D_ + ld0;
        const float* Vg = Vb + (size_t)(j * 64 + lrow) * D_ + ld0;
        #pragma unroll
        for (int rep = 0; rep < 4; rep++) {
            cp16(kb_ + (unsigned)(lrow * QST_ + ld0 + rep * 4) * 4, Kg + rep * 4);
            cp16(vb_ + (unsigned)(lrow * VST_ + ld0 + rep * 4) * 4, Vg + rep * 4);
        }
        CP_COMMIT();
    };

    // Q load (once) + KV tile 0
    {
        unsigned qs_ = (unsigned)__cvta_generic_to_shared(Qs);
        const float* Qg = Qb + (size_t)(qb + lrow) * D_ + ld0;
        #pragma unroll
        for (int rep = 0; rep < 4; rep++)
            cp16(qs_ + (unsigned)(lrow * QST_ + ld0 + rep * 4) * 4, Qg + rep * 4);
        CP_COMMIT();
    }
    issue_kv(0, 0);
    cp_wait<0>();
    __syncthreads();

    float acc[4][4];
    float m_i[2], l_i[2];
    m_i[0] = m_i[1] = -1e30f;
    l_i[0] = l_i[1] = 0.f;
    #pragma unroll
    for (int nf = 0; nf < 4; nf++)
        #pragma unroll
        for (int c = 0; c < 4; c++) acc[nf][c] = 0.f;

    const int r0l = wm + qm;
    const int ntile = blockIdx.x + 1;

    for (int j = 0; j < ntile; j++) {
        const int s = j & 1;
        if (j + 1 < ntile) issue_kv(j + 1, s ^ 1);

        const float* Ksb = &Ks[s * 64 * QST_];
        const float* Vsb = &Vs[s * 64 * VST_];

        // ---- S = Q @ K^T ----
        float sv4[4][4];
        #pragma unroll
        for (int nf = 0; nf < 4; nf++)
            #pragma unroll
            for (int c = 0; c < 4; c++) sv4[nf][c] = 0.f;

        #pragma unroll
        for (int ks = 0; ks < 8; ks++) {
            const int kk = ks * 8;
            unsigned a0 = __float_as_uint(Qs[(size_t)r0l * QST_ + kk + qk]);
            unsigned a1 = __float_as_uint(Qs[(size_t)(r0l + 8) * QST_ + kk + qk]);
            unsigned a2 = __float_as_uint(Qs[(size_t)r0l * QST_ + kk + qk + 4]);
            unsigned a3 = __float_as_uint(Qs[(size_t)(r0l + 8) * QST_ + kk + qk + 4]);
            #pragma unroll
            for (int nf = 0; nf < 4; nf++) {
                int n = wnh * 32 + nf * 8 + qm;
                unsigned b0 = __float_as_uint(Ksb[(size_t)n * QST_ + kk + qk]);
                unsigned b1 = __float_as_uint(Ksb[(size_t)n * QST_ + kk + qk + 4]);
                mma_tf32(sv4[nf], a0, a1, a2, a3, b0, b1);
            }
        }

        const bool diag = ((j * 64) == qb);
        #pragma unroll
        for (int nf = 0; nf < 4; nf++) {
            int colb = wnh * 32 + nf * 8 + 2 * qk;
            #pragma unroll
            for (int c = 0; c < 4; c++) {
                int col = colb + (c & 1);
                int row = r0l + ((c >> 1) ? 8 : 0);
                float sv = sv4[nf][c] * 0.125f;
                if (diag && (col > row)) sv = -1e30f;
                sv4[nf][c] = sv;
            }
        }

        // row max
        float mx0 = -1e30f, mx1 = -1e30f;
        #pragma unroll
        for (int nf = 0; nf < 4; nf++) {
            mx0 = fmaxf(mx0, fmaxf(sv4[nf][0], sv4[nf][1]));
            mx1 = fmaxf(mx1, fmaxf(sv4[nf][2], sv4[nf][3]));
        }
        #pragma unroll
        for (int o = 1; o < 4; o <<= 1) {
            mx0 = fmaxf(mx0, __shfl_xor_sync(0xffffffffu, mx0, o));
            mx1 = fmaxf(mx1, __shfl_xor_sync(0xffffffffu, mx1, o));
        }
        if ((lane & 3) == 0) {
            redmx[wnh * 64 + r0l]     = mx0;
            redmx[wnh * 64 + r0l + 8] = mx1;
        }
        __syncthreads();
        float mn0 = fmaxf(m_i[0], fmaxf(redmx[r0l],     redmx[64 + r0l]));
        float mn1 = fmaxf(m_i[1], fmaxf(redmx[r0l + 8], redmx[64 + r0l + 8]));

        // p = exp(s - mn); Ps tf32; row sums
        float sum0 = 0.f, sum1 = 0.f;
        #pragma unroll
        for (int nf = 0; nf < 4; nf++) {
            int colb = wnh * 32 + nf * 8 + 2 * qk;
            float p0 = __expf(sv4[nf][0] - mn0);
            float p1 = __expf(sv4[nf][1] - mn0);
            float p2 = __expf(sv4[nf][2] - mn1);
            float p3 = __expf(sv4[nf][3] - mn1);
            sum0 += p0 + p1;
            sum1 += p2 + p3;
            Ps[(size_t)r0l * QST_ + colb]           = f2tf32f(p0);
            Ps[(size_t)r0l * QST_ + colb + 1]       = f2tf32f(p1);
            Ps[(size_t)(r0l + 8) * QST_ + colb]     = f2tf32f(p2);
            Ps[(size_t)(r0l + 8) * QST_ + colb + 1] = f2tf32f(p3);
        }
        #pragma unroll
        for (int o = 1; o < 4; o <<= 1) {
            sum0 += __shfl_xor_sync(0xffffffffu, sum0, o);
            sum1 += __shfl_xor_sync(0xffffffffu, sum1, o);
        }
        if ((lane & 3) == 0) {
            redsm[wnh * 64 + r0l]     = sum0;
            redsm[wnh * 64 + r0l + 8] = sum1;
        }
        __syncthreads();
        float ts0 = redsm[r0l]     + redsm[64 + r0l];
        float ts1 = redsm[r0l + 8] + redsm[64 + r0l + 8];

        float al0 = __expf(m_i[0] - mn0);
        float al1 = __expf(m_i[1] - mn1);
        l_i[0] = l_i[0] * al0 + ts0;  m_i[0] = mn0;
        l_i[1] = l_i[1] * al1 + ts1;  m_i[1] = mn1;
        #pragma unroll
        for (int nf = 0; nf < 4; nf++) {
            acc[nf][0] *= al0; acc[nf][1] *= al0;
            acc[nf][2] *= al1; acc[nf][3] *= al1;
        }

        // ---- O += P @ V ----
        #pragma unroll
        for (int ks = 0; ks < 8; ks++) {
            const int kk = ks * 8;
            unsigned a0 = __float_as_uint(Ps[(size_t)r0l * QST_ + kk + qk]);
            unsigned a1 = __float_as_uint(Ps[(size_t)(r0l + 8) * QST_ + kk + qk]);
            unsigned a2 = __float_as_uint(Ps[(size_t)r0l * QST_ + kk + qk + 4]);
            unsigned a3 = __float_as_uint(Ps[(size_t)(r0l + 8) * QST_ + kk + qk + 4]);
            #pragma unroll
            for (int nf = 0; nf < 4; nf++) {
                int n = wnh * 32 + nf * 8 + qm;
                unsigned b0 = __float_as_uint(Vsb[(size_t)(kk + qk) * VST_ + n]);
                unsigned b1 = __float_as_uint(Vsb[(size_t)(kk + qk + 4) * VST_ + n]);
                mma_tf32(acc[nf], a0, a1, a2, a3, b0, b1);
            }
        }

        if (j + 1 < ntile) cp_wait<0>();
        __syncthreads();   // loads landed; Ps/Ks/Vs free for next iter
    }

    {
        float inv0 = 1.0f / l_i[0], inv1 = 1.0f / l_i[1];
        #pragma unroll
        for (int nf = 0; nf < 4; nf++) {
            int col = h * HD_ + wnh * 32 + nf * 8 + 2 * qk;
            size_t off0 = (size_t)b * T_ * D_ + (size_t)(qb + r0l) * D_ + col;
            size_t off1 = (size_t)b * T_ * D_ + (size_t)(qb + r0l + 8) * D_ + col;
            float2 o0 = make_float2(f2tf32f(acc[nf][0] * inv0), f2tf32f(acc[nf][1] * inv0));
            float2 o1 = make_float2(f2tf32f(acc[nf][2] * inv1), f2tf32f(acc[nf][3] * inv1));
            *reinterpret_cast<float2*>(const_cast<float*>(O) + off0) = o0;
            *reinterpret_cast<float2*>(const_cast<float*>(O) + off1) = o1;
        }
    }
}

// ---------------------------------------------------------------------------
// Orchestration
// ---------------------------------------------------------------------------
extern "C" void kernel_launch(void* const* d_in, const int* in_sizes, int n_in,
                              void* d_out, int out_size)
{
    const float* h    = (const float*)d_in[0];
    const float* alng = (const float*)d_in[2];
    const float* alnb = (const float*)d_in[3];
    const float* mlng = (const float*)d_in[4];
    const float* mlnb = (const float*)d_in[5];
    const float* wq   = (const float*)d_in[6];
    const float* wk   = (const float*)d_in[7];
    const float* wv   = (const float*)d_in[8];
    const float* wo   = (const float*)d_in[9];
    const float* w1   = (const float*)d_in[10];
    const float* w2   = (const float*)d_in[11];
    const float* wout = (const float*)d_in[12];
    float* out = (float*)d_out;

    float *px, *pq, *pk, *pv, *po, *ph2, *py, *pa;
    float *rwq, *rwk, *rwv, *rwo, *rw1, *rw2, *rwout;
    cudaGetSymbolAddress((void**)&px,  g_x);
    cudaGetSymbolAddress((void**)&pq,  g_q);
    cudaGetSymbolAddress((void**)&pk,  g_k);
    cudaGetSymbolAddress((void**)&pv,  g_v);
    cudaGetSymbolAddress((void**)&po,  g_o);
    cudaGetSymbolAddress((void**)&ph2, g_h2);
    cudaGetSymbolAddress((void**)&py,  g_y);
    cudaGetSymbolAddress((void**)&pa,  g_a);
    cudaGetSymbolAddress((void**)&rwq,   g_wq);
    cudaGetSymbolAddress((void**)&rwk,   g_wk);
    cudaGetSymbolAddress((void**)&rwv,   g_wv);
    cudaGetSymbolAddress((void**)&rwo,   g_wo);
    cudaGetSymbolAddress((void**)&rw1,   g_w1);
    cudaGetSymbolAddress((void**)&rw2,   g_w2);
    cudaGetSymbolAddress((void**)&rwout, g_wout);

    cudaFuncSetAttribute(attn_kernel, cudaFuncAttributeMaxDynamicSharedMemorySize, ATTN_SMEM);
    cudaFuncSetAttribute(ffn_kernel,  cudaFuncAttributeMaxDynamicSharedMemorySize, GEMM_SMEM);
    cudaFuncSetAttribute(tgemm_kernel<false, true, 3>, cudaFuncAttributeMaxDynamicSharedMemorySize, GEMM_SMEM);
    cudaFuncSetAttribute(tgemm_kernel<true, false, 1>, cudaFuncAttributeMaxDynamicSharedMemorySize, GEMM_SMEM);

    // tf32-round weights
    round_kernel<<<(D_ * D_ / 4) / 256, 256>>>(wq, rwq);
    round_kernel<<<(D_ * D_ / 4) / 256, 256>>>(wk, rwk);
    round_kernel<<<(D_ * D_ / 4) / 256, 256>>>(wv, rwv);
    round_kernel<<<(D_ * D_ / 4) / 256, 256>>>(wo, rwo);
    round_kernel<<<(D_ * FFN_ / 4) / 256, 256>>>(w1, rw1);
    round_kernel<<<(D_ * FFN_ / 4) / 256, 256>>>(w2, rw2);
    round_kernel<<<(FFN_ * D_ / 4) / 256, 256>>>(wout, rwout);

    dim3 gQKV(D_ / 128, ROWS_ / 128, 3);    // (8, 64, 3)
    dim3 gD(D_ / 128, ROWS_ / 128);         // (8, 64)
    dim3 gFFN(FFN_ / 64, ROWS_ / 128);      // (64, 64)

    // x = tf32(LN(h))
    ln_kernel<<<ROWS_, 256>>>(h, alng, alnb, px);
    // q,k,v = tf32(x @ {wq,wk,wv})
    tgemm_kernel<false, true, 3><<<gQKV, 256, GEMM_SMEM>>>(px, rwq, rwk, rwv, nullptr,
                                                           pq, pk, pv, ROWS_, D_, D_);
    // o = tf32(attention(q,k,v))
    attn_kernel<<<dim3(T_ / 64, B_ * H_), 256, ATTN_SMEM>>>(pq, pk, pv, po);
    // h2 = h + o @ wo
    tgemm_kernel<true, false, 1><<<gD, 256, GEMM_SMEM>>>(po, rwo, nullptr, nullptr, h,
                                                         ph2, nullptr, nullptr, ROWS_, D_, D_);
    // y = tf32(LN(h2))
    ln_kernel<<<ROWS_, 256>>>(ph2, mlng, mlnb, py);
    // a = tf32(silu(y@w1) * (y@w2))   (fused dual GEMM + SiLU)
    ffn_kernel<<<gFFN, 256, GEMM_SMEM>>>(py, rw1, rw2, pa, ROWS_, FFN_, D_);
    // out = h2 + a @ wout
    tgemm_kernel<true, false, 1><<<gD, 256, GEMM_SMEM>>>(pa, rwout, nullptr, nullptr, ph2,
                                                         out, nullptr, nullptr, ROWS_, D_, FFN_);
}